// round 2
// baseline (speedup 1.0000x reference)
#include <cuda_runtime.h>
#include <math.h>

#define GXD 128
#define GYD 128
#define GZD 128
#define VDIM 28
#define NRAYS 8192
#define NSAMP 128
#define NVOX (GXD*GYD*GZD)

// Reduced grid: per-voxel {sigma, r, g, b} after SH contraction. 33.5 MB — fits in L2.
__device__ float4 g_red[NVOX];

__global__ void prepass_kernel(const float* __restrict__ grid,
                               const float* __restrict__ ang) {
    int v = blockIdx.x * blockDim.x + threadIdx.x;
    if (v >= NVOX) return;

    float theta = ang[0], phi = ang[1];
    float st, ct, sp, cp;
    sincosf(theta, &st, &ct);
    sincosf(phi, &sp, &cp);

    const float y00 = 0.28209479177387814f;   // 0.5*sqrt(1/pi)
    const float h3  = 0.4886025119029199f;    // 0.5*sqrt(3/pi)
    const float q5  = 0.31539156525252005f;   // 0.25*sqrt(5/pi)
    const float h15 = 1.0925484305920792f;    // 0.5*sqrt(15/pi)
    const float q15 = 0.5462742152960396f;    // 0.25*sqrt(15/pi)

    float b[9];
    b[0] = y00;
    b[1] = h3 * st * sp;
    b[2] = h3 * ct;
    b[3] = h3 * st * cp;
    b[4] = h15 * st * cp * st * sp;
    b[5] = h15 * st * sp * ct;
    b[6] = q5 * (3.0f * ct * ct - 1.0f);
    b[7] = h15 * st * cp * ct;
    b[8] = q15 * ((st * cp) * (st * cp) - (st * sp) * (st * sp));

    const float* f = grid + (size_t)v * VDIM;
    float sigma = f[0];
    float r = 0.f, g = 0.f, bl = 0.f;
#pragma unroll
    for (int k = 0; k < 9; k++) {
        float bk = b[k];
        r  += f[1 + k]  * bk;
        g  += f[10 + k] * bk;
        bl += f[19 + k] * bk;
    }
    g_red[v] = make_float4(sigma, r, g, bl);
}

__device__ __forceinline__ float4 lerp4(float4 a, float4 b, float t) {
    return make_float4(a.x + (b.x - a.x) * t,
                       a.y + (b.y - a.y) * t,
                       a.z + (b.z - a.z) * t,
                       a.w + (b.w - a.w) * t);
}

// One warp per ray; lane handles samples [4*lane, 4*lane+4).
__global__ void render_kernel(const float* __restrict__ pos,
                              const float* __restrict__ dist,
                              float* __restrict__ out) {
    int warp_in_block = threadIdx.x >> 5;
    int lane = threadIdx.x & 31;
    int ray = blockIdx.x * (blockDim.x >> 5) + warp_in_block;
    if (ray >= NRAYS) return;

    // Load 4 samples' positions: 12 contiguous floats, 16B-aligned.
    const float4* pv = reinterpret_cast<const float4*>(pos + (size_t)ray * NSAMP * 3) + lane * 3;
    float4 pa = pv[0];
    float4 pb = pv[1];
    float4 pc = pv[2];
    float q[12] = {pa.x, pa.y, pa.z, pa.w, pb.x, pb.y, pb.z, pb.w, pc.x, pc.y, pc.z, pc.w};

    float4 dd = reinterpret_cast<const float4*>(dist + (size_t)ray * NSAMP)[lane];
    float dv[4] = {dd.x, dd.y, dd.z, dd.w};

    // Compute all 4 bases + fractions first, then issue all 32 loads, then math.
    int bases[4];
    float xdv[4], ydv[4], zdv[4];
#pragma unroll
    for (int i = 0; i < 4; i++) {
        float x = q[i * 3 + 0];
        float y = q[i * 3 + 1];
        float z = q[i * 3 + 2];
        float fx = floorf(x), fy = floorf(y), fz = floorf(z);
        int x0 = (int)fx, y0 = (int)fy, z0 = (int)fz;
        xdv[i] = x - fx; ydv[i] = y - fy; zdv[i] = z - fz;
        bases[i] = (x0 * GYD + y0) * GZD + z0;
    }

    float4 c[4][8];
#pragma unroll
    for (int i = 0; i < 4; i++) {
        const float4* G = g_red + bases[i];
        c[i][0] = G[0];
        c[i][1] = G[1];
        c[i][2] = G[GZD];
        c[i][3] = G[GZD + 1];
        c[i][4] = G[GYD * GZD];
        c[i][5] = G[GYD * GZD + 1];
        c[i][6] = G[GYD * GZD + GZD];
        c[i][7] = G[GYD * GZD + GZD + 1];
    }

    float att[4], rr[4], gg[4], bb[4];
    float localsum = 0.f;
#pragma unroll
    for (int i = 0; i < 4; i++) {
        float xd = xdv[i], yd = ydv[i], zd = zdv[i];
        float4 c00 = lerp4(c[i][0], c[i][4], xd);
        float4 c01 = lerp4(c[i][1], c[i][5], xd);
        float4 c10 = lerp4(c[i][2], c[i][6], xd);
        float4 c11 = lerp4(c[i][3], c[i][7], xd);
        float4 c0 = lerp4(c00, c10, yd);
        float4 c1 = lerp4(c01, c11, yd);
        float4 cf = lerp4(c0, c1, zd);

        float tau = cf.x * dv[i];
        float a = expf(-tau);
        att[i] = a;
        localsum += a;
        rr[i] = cf.y;
        gg[i] = cf.z;
        bb[i] = cf.w;
    }

    // Warp inclusive scan of per-thread att sums -> exclusive prefix.
    float s = localsum;
#pragma unroll
    for (int off = 1; off < 32; off <<= 1) {
        float n = __shfl_up_sync(0xffffffffu, s, off);
        if (lane >= off) s += n;
    }
    float excl = s - localsum;

    float ox = 0.f, oy = 0.f, oz = 0.f;
    float acc = excl;
#pragma unroll
    for (int i = 0; i < 4; i++) {
        acc += att[i];                       // inclusive cumsum (transmittance)
        float w = acc * (1.0f - att[i]);     // transmittance * alpha
        ox += w * rr[i];
        oy += w * gg[i];
        oz += w * bb[i];
    }

    // Warp reduction of the 3-channel accumulator.
#pragma unroll
    for (int off = 16; off > 0; off >>= 1) {
        ox += __shfl_down_sync(0xffffffffu, ox, off);
        oy += __shfl_down_sync(0xffffffffu, oy, off);
        oz += __shfl_down_sync(0xffffffffu, oz, off);
    }
    if (lane == 0) {
        out[(size_t)ray * 3 + 0] = ox;
        out[(size_t)ray * 3 + 1] = oy;
        out[(size_t)ray * 3 + 2] = oz;
    }
}

extern "C" void kernel_launch(void* const* d_in, const int* in_sizes, int n_in,
                              void* d_out, int out_size) {
    const float* voxel_grid = (const float*)d_in[0];
    const float* sample_pos = (const float*)d_in[1];
    const float* sample_dist = (const float*)d_in[2];
    const float* view_ang = (const float*)d_in[3];
    float* out = (float*)d_out;

    {
        int threads = 256;
        int blocks = (NVOX + threads - 1) / threads;
        prepass_kernel<<<blocks, threads>>>(voxel_grid, view_ang);
    }
    {
        int threads = 256;                       // 8 warps = 8 rays per block
        int blocks = NRAYS / (threads / 32);     // 1024
        render_kernel<<<blocks, threads>>>(sample_pos, sample_dist, out);
    }
}

// round 4
// speedup vs baseline: 1.3156x; 1.3156x over previous
#include <cuda_runtime.h>
#include <cuda_fp16.h>
#include <math.h>

#define GXD 128
#define GYD 128
#define GZD 128
#define VDIM 28
#define NRAYS 8192
#define NSAMP 128
#define NVOX (GXD*GYD*GZD)

// Reduced fp16 grids: per-voxel half4 {sigma, r, g, b} = 8 B.
// g_E[v]   = voxel v                      (even-z pairs 16B-aligned)
// g_O[v-1] = voxel v  (z-shifted by -1)   (odd-z pairs 16B-aligned)
// Each stored as uint4 pairs (2 voxels = 16 B).
__device__ uint4 g_E[NVOX / 2];
__device__ uint4 g_O[NVOX / 2];

__device__ __forceinline__ unsigned h2_as_u(__half2 h) {
    return *reinterpret_cast<unsigned*>(&h);
}
__device__ __forceinline__ __half2 u_as_h2(unsigned u) {
    return *reinterpret_cast<__half2*>(&u);
}

#define PRE_T 256

__global__ void prepass_kernel(const float* __restrict__ grid,
                               const float* __restrict__ ang) {
    __shared__ float sh[PRE_T * VDIM];
    __shared__ float shb[9];

    if (threadIdx.x == 0) {
        float theta = ang[0], phi = ang[1];
        float st, ct, sp, cp;
        sincosf(theta, &st, &ct);
        sincosf(phi, &sp, &cp);
        const float y00 = 0.28209479177387814f;
        const float h3  = 0.4886025119029199f;
        const float q5  = 0.31539156525252005f;
        const float h15 = 1.0925484305920792f;
        const float q15 = 0.5462742152960396f;
        shb[0] = y00;
        shb[1] = h3 * st * sp;
        shb[2] = h3 * ct;
        shb[3] = h3 * st * cp;
        shb[4] = h15 * st * cp * st * sp;
        shb[5] = h15 * st * sp * ct;
        shb[6] = q5 * (3.0f * ct * ct - 1.0f);
        shb[7] = h15 * st * cp * ct;
        shb[8] = q15 * ((st * cp) * (st * cp) - (st * sp) * (st * sp));
    }

    int blockBase = blockIdx.x * PRE_T;
    // Coalesced staging: 256 voxels * 28 floats = 1792 float4, 7 per thread.
    const float4* src = reinterpret_cast<const float4*>(grid + (size_t)blockBase * VDIM);
    float4* s4 = reinterpret_cast<float4*>(sh);
#pragma unroll
    for (int k = 0; k < 7; k++)
        s4[threadIdx.x + PRE_T * k] = src[threadIdx.x + PRE_T * k];
    __syncthreads();

    float b[9];
#pragma unroll
    for (int k = 0; k < 9; k++) b[k] = shb[k];

    const float* f = sh + threadIdx.x * VDIM;
    float sigma = f[0];
    float r = 0.f, g = 0.f, bl = 0.f;
#pragma unroll
    for (int k = 0; k < 9; k++) {
        float bk = b[k];
        r  += f[1 + k]  * bk;
        g  += f[10 + k] * bk;
        bl += f[19 + k] * bk;
    }

    uint2 h;
    h.x = h2_as_u(__floats2half2_rn(sigma, r));
    h.y = h2_as_u(__floats2half2_rn(g, bl));

    int v = blockBase + threadIdx.x;
    reinterpret_cast<uint2*>(g_E)[v] = h;
    if (v > 0) reinterpret_cast<uint2*>(g_O)[v - 1] = h;
}

// One warp per ray; lane handles samples [4*lane, 4*lane+4).
__global__ void render_kernel(const float* __restrict__ pos,
                              const float* __restrict__ dist,
                              float* __restrict__ out) {
    int warp_in_block = threadIdx.x >> 5;
    int lane = threadIdx.x & 31;
    int ray = blockIdx.x * (blockDim.x >> 5) + warp_in_block;
    if (ray >= NRAYS) return;

    const float4* pv = reinterpret_cast<const float4*>(pos + (size_t)ray * NSAMP * 3) + lane * 3;
    float4 pa = pv[0];
    float4 pb = pv[1];
    float4 pc = pv[2];
    float q[12] = {pa.x, pa.y, pa.z, pa.w, pb.x, pb.y, pb.z, pb.w, pc.x, pc.y, pc.z, pc.w};

    float4 dd = reinterpret_cast<const float4*>(dist + (size_t)ray * NSAMP)[lane];
    float dv[4] = {dd.x, dd.y, dd.z, dd.w};

    float att[4], rr[4], gg[4], bb[4];
    float localsum = 0.f;

#pragma unroll
    for (int i = 0; i < 4; i++) {
        float x = q[i * 3 + 0];
        float y = q[i * 3 + 1];
        float z = q[i * 3 + 2];
        float fx = floorf(x), fy = floorf(y), fz = floorf(z);
        int x0 = (int)fx, y0 = (int)fy, z0 = (int)fz;
        float xd = x - fx, yd = y - fy, zd = z - fz;

        int base = (x0 * GYD + y0) * GZD + (z0 & ~1);
        const uint4* P = (z0 & 1) ? g_O : g_E;
        int pi = base >> 1;

        // Four 16B pair loads (each = voxels z0, z0+1 for one (x,y) corner).
        uint4 p00 = P[pi];
        uint4 p01 = P[pi + (GZD >> 1)];
        uint4 p10 = P[pi + (GYD * GZD >> 1)];
        uint4 p11 = P[pi + ((GYD * GZD + GZD) >> 1)];

        // z-lerp within each pair (fp32).
        float4 c00, c01, c10, c11;
        {
            float2 a0 = __half22float2(u_as_h2(p00.x)), a1 = __half22float2(u_as_h2(p00.y));
            float2 b0 = __half22float2(u_as_h2(p00.z)), b1 = __half22float2(u_as_h2(p00.w));
            c00 = make_float4(a0.x + (b0.x - a0.x) * zd, a0.y + (b0.y - a0.y) * zd,
                              a1.x + (b1.x - a1.x) * zd, a1.y + (b1.y - a1.y) * zd);
        }
        {
            float2 a0 = __half22float2(u_as_h2(p01.x)), a1 = __half22float2(u_as_h2(p01.y));
            float2 b0 = __half22float2(u_as_h2(p01.z)), b1 = __half22float2(u_as_h2(p01.w));
            c01 = make_float4(a0.x + (b0.x - a0.x) * zd, a0.y + (b0.y - a0.y) * zd,
                              a1.x + (b1.x - a1.x) * zd, a1.y + (b1.y - a1.y) * zd);
        }
        {
            float2 a0 = __half22float2(u_as_h2(p10.x)), a1 = __half22float2(u_as_h2(p10.y));
            float2 b0 = __half22float2(u_as_h2(p10.z)), b1 = __half22float2(u_as_h2(p10.w));
            c10 = make_float4(a0.x + (b0.x - a0.x) * zd, a0.y + (b0.y - a0.y) * zd,
                              a1.x + (b1.x - a1.x) * zd, a1.y + (b1.y - a1.y) * zd);
        }
        {
            float2 a0 = __half22float2(u_as_h2(p11.x)), a1 = __half22float2(u_as_h2(p11.y));
            float2 b0 = __half22float2(u_as_h2(p11.z)), b1 = __half22float2(u_as_h2(p11.w));
            c11 = make_float4(a0.x + (b0.x - a0.x) * zd, a0.y + (b0.y - a0.y) * zd,
                              a1.x + (b1.x - a1.x) * zd, a1.y + (b1.y - a1.y) * zd);
        }

        // y-lerp then x-lerp.
        float4 c0 = make_float4(c00.x + (c01.x - c00.x) * yd, c00.y + (c01.y - c00.y) * yd,
                                c00.z + (c01.z - c00.z) * yd, c00.w + (c01.w - c00.w) * yd);
        float4 c1 = make_float4(c10.x + (c11.x - c10.x) * yd, c10.y + (c11.y - c10.y) * yd,
                                c10.z + (c11.z - c10.z) * yd, c10.w + (c11.w - c10.w) * yd);
        float4 cf = make_float4(c0.x + (c1.x - c0.x) * xd, c0.y + (c1.y - c0.y) * xd,
                                c0.z + (c1.z - c0.z) * xd, c0.w + (c1.w - c0.w) * xd);

        float tau = cf.x * dv[i];
        float a = __expf(-tau);
        att[i] = a;
        localsum += a;
        rr[i] = cf.y;
        gg[i] = cf.z;
        bb[i] = cf.w;
    }

    // Warp inclusive scan of per-thread att sums -> exclusive prefix.
    float s = localsum;
#pragma unroll
    for (int off = 1; off < 32; off <<= 1) {
        float n = __shfl_up_sync(0xffffffffu, s, off);
        if (lane >= off) s += n;
    }
    float excl = s - localsum;

    float ox = 0.f, oy = 0.f, oz = 0.f;
    float acc = excl;
#pragma unroll
    for (int i = 0; i < 4; i++) {
        acc += att[i];                       // inclusive cumsum (transmittance)
        float w = acc * (1.0f - att[i]);     // transmittance * alpha
        ox += w * rr[i];
        oy += w * gg[i];
        oz += w * bb[i];
    }

#pragma unroll
    for (int off = 16; off > 0; off >>= 1) {
        ox += __shfl_down_sync(0xffffffffu, ox, off);
        oy += __shfl_down_sync(0xffffffffu, oy, off);
        oz += __shfl_down_sync(0xffffffffu, oz, off);
    }
    if (lane == 0) {
        out[(size_t)ray * 3 + 0] = ox;
        out[(size_t)ray * 3 + 1] = oy;
        out[(size_t)ray * 3 + 2] = oz;
    }
}

extern "C" void kernel_launch(void* const* d_in, const int* in_sizes, int n_in,
                              void* d_out, int out_size) {
    const float* voxel_grid = (const float*)d_in[0];
    const float* sample_pos = (const float*)d_in[1];
    const float* sample_dist = (const float*)d_in[2];
    const float* view_ang = (const float*)d_in[3];
    float* out = (float*)d_out;

    {
        int blocks = NVOX / PRE_T;               // 8192
        prepass_kernel<<<blocks, PRE_T>>>(voxel_grid, view_ang);
    }
    {
        int threads = 256;                       // 8 warps = 8 rays per block
        int blocks = NRAYS / (threads / 32);     // 1024
        render_kernel<<<blocks, threads>>>(sample_pos, sample_dist, out);
    }
}

// round 8
// speedup vs baseline: 1.3204x; 1.0037x over previous
#include <cuda_runtime.h>
#include <cuda_fp16.h>
#include <math.h>

#define GXD 128
#define GYD 128
#define GZD 128
#define VDIM 28
#define NRAYS 8192
#define NSAMP 128
#define NVOX (GXD*GYD*GZD)

// Reduced fp16 grids: per-voxel half4 {sigma, r, g, b} = 8 B.
// g_E[v]   = voxel v                      (even-z pairs 16B-aligned)
// g_O[v-1] = voxel v  (z-shifted by -1)   (odd-z pairs 16B-aligned)
__device__ uint4 g_E[NVOX / 2];
__device__ uint4 g_O[NVOX / 2];

__device__ __forceinline__ unsigned h2_as_u(__half2 h) {
    return *reinterpret_cast<unsigned*>(&h);
}
__device__ __forceinline__ __half2 u_as_h2(unsigned u) {
    return *reinterpret_cast<__half2*>(&u);
}

#define PRE_T 256

__global__ void prepass_kernel(const float* __restrict__ grid,
                               const float* __restrict__ ang) {
    __shared__ float sh[PRE_T * VDIM];
    __shared__ float shb[9];

    if (threadIdx.x == 0) {
        float theta = ang[0], phi = ang[1];
        float st, ct, sp, cp;
        sincosf(theta, &st, &ct);
        sincosf(phi, &sp, &cp);
        const float y00 = 0.28209479177387814f;
        const float h3  = 0.4886025119029199f;
        const float q5  = 0.31539156525252005f;
        const float h15 = 1.0925484305920792f;
        const float q15 = 0.5462742152960396f;
        shb[0] = y00;
        shb[1] = h3 * st * sp;
        shb[2] = h3 * ct;
        shb[3] = h3 * st * cp;
        shb[4] = h15 * st * cp * st * sp;
        shb[5] = h15 * st * sp * ct;
        shb[6] = q5 * (3.0f * ct * ct - 1.0f);
        shb[7] = h15 * st * cp * ct;
        shb[8] = q15 * ((st * cp) * (st * cp) - (st * sp) * (st * sp));
    }

    int blockBase = blockIdx.x * PRE_T;
    const float4* src = reinterpret_cast<const float4*>(grid + (size_t)blockBase * VDIM);
    float4* s4 = reinterpret_cast<float4*>(sh);
#pragma unroll
    for (int k = 0; k < 7; k++)
        s4[threadIdx.x + PRE_T * k] = src[threadIdx.x + PRE_T * k];
    __syncthreads();

    float b[9];
#pragma unroll
    for (int k = 0; k < 9; k++) b[k] = shb[k];

    const float* f = sh + threadIdx.x * VDIM;
    float sigma = f[0];
    float r = 0.f, g = 0.f, bl = 0.f;
#pragma unroll
    for (int k = 0; k < 9; k++) {
        float bk = b[k];
        r  += f[1 + k]  * bk;
        g  += f[10 + k] * bk;
        bl += f[19 + k] * bk;
    }

    uint2 h;
    h.x = h2_as_u(__floats2half2_rn(sigma, r));
    h.y = h2_as_u(__floats2half2_rn(g, bl));

    int v = blockBase + threadIdx.x;
    reinterpret_cast<uint2*>(g_E)[v] = h;
    if (v > 0) reinterpret_cast<uint2*>(g_O)[v - 1] = h;
}

// One warp per ray; lane handles samples [4*lane, 4*lane+4).
// All 16 pair-loads hoisted before any lerp math: MLP=16 per thread.
__global__ void __launch_bounds__(256, 8)
render_kernel(const float* __restrict__ pos,
              const float* __restrict__ dist,
              float* __restrict__ out) {
    int warp_in_block = threadIdx.x >> 5;
    int lane = threadIdx.x & 31;
    int ray = blockIdx.x * (blockDim.x >> 5) + warp_in_block;
    if (ray >= NRAYS) return;

    const float4* pv = reinterpret_cast<const float4*>(pos + (size_t)ray * NSAMP * 3) + lane * 3;
    float4 pa = pv[0];
    float4 pb = pv[1];
    float4 pc = pv[2];
    float q[12] = {pa.x, pa.y, pa.z, pa.w, pb.x, pb.y, pb.z, pb.w, pc.x, pc.y, pc.z, pc.w};

    float4 dd = reinterpret_cast<const float4*>(dist + (size_t)ray * NSAMP)[lane];
    float dv[4] = {dd.x, dd.y, dd.z, dd.w};

    // Phase 1: address generation for all 4 samples.
    const uint4* Pv[4];
    int piv[4];
    float xdv[4], ydv[4], zdv[4];
#pragma unroll
    for (int i = 0; i < 4; i++) {
        float x = q[i * 3 + 0];
        float y = q[i * 3 + 1];
        float z = q[i * 3 + 2];
        float fx = floorf(x), fy = floorf(y), fz = floorf(z);
        int x0 = (int)fx, y0 = (int)fy, z0 = (int)fz;
        xdv[i] = x - fx; ydv[i] = y - fy; zdv[i] = z - fz;
        int base = (x0 * GYD + y0) * GZD + (z0 & ~1);
        Pv[i] = (z0 & 1) ? g_O : g_E;
        piv[i] = base >> 1;
    }

    // Phase 2: issue all 16 pair loads back-to-back.
    uint4 p[4][4];
#pragma unroll
    for (int i = 0; i < 4; i++) {
        const uint4* P = Pv[i];
        int pi = piv[i];
        p[i][0] = P[pi];
        p[i][1] = P[pi + (GZD >> 1)];
        p[i][2] = P[pi + (GYD * GZD >> 1)];
        p[i][3] = P[pi + ((GYD * GZD + GZD) >> 1)];
    }

    // Phase 3: all math.
    float att[4], rr[4], gg[4], bb[4];
    float localsum = 0.f;
#pragma unroll
    for (int i = 0; i < 4; i++) {
        float xd = xdv[i], yd = ydv[i], zd = zdv[i];
        float4 c[4];
#pragma unroll
        for (int j = 0; j < 4; j++) {
            float2 a0 = __half22float2(u_as_h2(p[i][j].x));
            float2 a1 = __half22float2(u_as_h2(p[i][j].y));
            float2 b0 = __half22float2(u_as_h2(p[i][j].z));
            float2 b1 = __half22float2(u_as_h2(p[i][j].w));
            c[j] = make_float4(a0.x + (b0.x - a0.x) * zd, a0.y + (b0.y - a0.y) * zd,
                               a1.x + (b1.x - a1.x) * zd, a1.y + (b1.y - a1.y) * zd);
        }
        float4 c0 = make_float4(c[0].x + (c[1].x - c[0].x) * yd, c[0].y + (c[1].y - c[0].y) * yd,
                                c[0].z + (c[1].z - c[0].z) * yd, c[0].w + (c[1].w - c[0].w) * yd);
        float4 c1 = make_float4(c[2].x + (c[3].x - c[2].x) * yd, c[2].y + (c[3].y - c[2].y) * yd,
                                c[2].z + (c[3].z - c[2].z) * yd, c[2].w + (c[3].w - c[2].w) * yd);
        float4 cf = make_float4(c0.x + (c1.x - c0.x) * xd, c0.y + (c1.y - c0.y) * xd,
                                c0.z + (c1.z - c0.z) * xd, c0.w + (c1.w - c0.w) * xd);

        float tau = cf.x * dv[i];
        float a = __expf(-tau);
        att[i] = a;
        localsum += a;
        rr[i] = cf.y;
        gg[i] = cf.z;
        bb[i] = cf.w;
    }

    // Warp inclusive scan of per-thread att sums -> exclusive prefix.
    float s = localsum;
#pragma unroll
    for (int off = 1; off < 32; off <<= 1) {
        float n = __shfl_up_sync(0xffffffffu, s, off);
        if (lane >= off) s += n;
    }
    float excl = s - localsum;

    float ox = 0.f, oy = 0.f, oz = 0.f;
    float acc = excl;
#pragma unroll
    for (int i = 0; i < 4; i++) {
        acc += att[i];                       // inclusive cumsum (transmittance)
        float w = acc * (1.0f - att[i]);     // transmittance * alpha
        ox += w * rr[i];
        oy += w * gg[i];
        oz += w * bb[i];
    }

#pragma unroll
    for (int off = 16; off > 0; off >>= 1) {
        ox += __shfl_down_sync(0xffffffffu, ox, off);
        oy += __shfl_down_sync(0xffffffffu, oy, off);
        oz += __shfl_down_sync(0xffffffffu, oz, off);
    }
    if (lane == 0) {
        out[(size_t)ray * 3 + 0] = ox;
        out[(size_t)ray * 3 + 1] = oy;
        out[(size_t)ray * 3 + 2] = oz;
    }
}

extern "C" void kernel_launch(void* const* d_in, const int* in_sizes, int n_in,
                              void* d_out, int out_size) {
    const float* voxel_grid = (const float*)d_in[0];
    const float* sample_pos = (const float*)d_in[1];
    const float* sample_dist = (const float*)d_in[2];
    const float* view_ang = (const float*)d_in[3];
    float* out = (float*)d_out;

    {
        int blocks = NVOX / PRE_T;               // 8192
        prepass_kernel<<<blocks, PRE_T>>>(voxel_grid, view_ang);
    }
    {
        int threads = 256;                       // 8 warps = 8 rays per block
        int blocks = NRAYS / (threads / 32);     // 1024
        render_kernel<<<blocks, threads>>>(sample_pos, sample_dist, out);
    }
}